// round 1
// baseline (speedup 1.0000x reference)
#include <cuda_runtime.h>
#include <cuda_bf16.h>

// Problem shape (fixed for GAT_40870908789103)
#define Nn   50000
#define Ee   800000
#define Fin  128
#define Hh   8
#define Oo   8
#define HO   64          // H*O
#define NEG_SLOPE 0.2f

// Scratch (no allocation allowed -> __device__ globals)
__device__ float g_Wh[(size_t)Nn * HO];     // projected features [N][64]
__device__ float g_ssrc[(size_t)Nn * Hh];   // a1 . Wh[n,h,:]
__device__ float g_sdst[(size_t)Nn * Hh];   // a2 . Wh[n,h,:]
__device__ float g_p[(size_t)Ee * Hh];      // exp(edge logits)
__device__ float g_denom[(size_t)Nn * Hh];  // softmax denominators

// ---------------------------------------------------------------------------
// K0: zero denominators
// ---------------------------------------------------------------------------
__global__ void k_zero_denom() {
    int i = blockIdx.x * blockDim.x + threadIdx.x;
    if (i < Nn * Hh) g_denom[i] = 0.0f;
}

// ---------------------------------------------------------------------------
// K1: Wh = h @ W (per head), plus per-node half-scores s_src, s_dst.
// 256 threads, 16 rows/block. Thread = (row r, head, half): computes 4
// consecutive outputs -> 1 scalar LDS + 1 LDS.128 per 4 FMAs.
// 50000 % 16 == 0, so no row guards needed.
// ---------------------------------------------------------------------------
__global__ __launch_bounds__(256) void k_proj(const float* __restrict__ h,
                                              const float* __restrict__ W,
                                              const float* __restrict__ a1,
                                              const float* __restrict__ a2) {
    __shared__ float Wt[Fin * HO];     // W transposed to [f][64], 32KB
    __shared__ float hs[16 * Fin];     // 16 input rows, 8KB
    __shared__ float a1s[HO], a2s[HO];

    const int tid = threadIdx.x;

    // Load + transpose W: W[h][f][o] -> Wt[f*64 + h*8 + o]
    for (int i = tid; i < Fin * HO; i += 256) {
        int hidx = i >> 10;        // / (Fin*Oo) = /1024
        int rem  = i & 1023;
        int f    = rem >> 3;
        int o    = rem & 7;
        Wt[f * 64 + hidx * 8 + o] = W[i];
    }
    if (tid < HO) { a1s[tid] = a1[tid]; a2s[tid] = a2[tid]; }

    const int row0 = blockIdx.x * 16;
    for (int i = tid; i < 16 * Fin; i += 256) {
        hs[i] = h[(size_t)(row0 + (i >> 7)) * Fin + (i & 127)];
    }
    __syncthreads();

    const int r    = tid >> 4;         // 0..15 row within chunk
    const int head = (tid >> 1) & 7;   // 0..7
    const int half = tid & 1;          // 0..1
    const int col  = head * 8 + half * 4;

    float4 acc = make_float4(0.f, 0.f, 0.f, 0.f);
    const float* hrow = &hs[r * Fin];
    #pragma unroll 16
    for (int f = 0; f < Fin; f++) {
        float  hv = hrow[f];
        float4 w  = *(const float4*)&Wt[f * 64 + col];
        acc.x += hv * w.x; acc.y += hv * w.y;
        acc.z += hv * w.z; acc.w += hv * w.w;
    }

    const int row = row0 + r;
    *(float4*)&g_Wh[(size_t)row * HO + col] = acc;

    float s1 = acc.x * a1s[col] + acc.y * a1s[col + 1] +
               acc.z * a1s[col + 2] + acc.w * a1s[col + 3];
    float s2 = acc.x * a2s[col] + acc.y * a2s[col + 1] +
               acc.z * a2s[col + 2] + acc.w * a2s[col + 3];
    s1 += __shfl_xor_sync(0xffffffffu, s1, 1);
    s2 += __shfl_xor_sync(0xffffffffu, s2, 1);
    if (half == 0) {
        g_ssrc[row * Hh + head] = s1;
        g_sdst[row * Hh + head] = s2;
    }
}

// ---------------------------------------------------------------------------
// K2: per (edge, head): p = exp(leaky_relu(s_src[src] + s_dst[dst])),
// accumulate denominators. Max-subtraction skipped (|e| <~ 30, no overflow;
// result analytically identical).
// ---------------------------------------------------------------------------
__global__ __launch_bounds__(256) void k_edge(const int* __restrict__ src,
                                              const int* __restrict__ dst) {
    int idx = blockIdx.x * 256 + threadIdx.x;
    if (idx >= Ee * Hh) return;
    int e = idx >> 3;
    int hh = idx & 7;
    int s = src[e];
    int d = dst[e];
    float ev = g_ssrc[s * Hh + hh] + g_sdst[d * Hh + hh];
    ev = ev > 0.0f ? ev : NEG_SLOPE * ev;
    float pv = __expf(ev);
    g_p[idx] = pv;
    atomicAdd(&g_denom[d * Hh + hh], pv);
}

// ---------------------------------------------------------------------------
// K4: weighted scatter. 16 threads/edge, each handles a float4 slice of the
// 64-float message; accumulate with vectorized no-return reductions.
// ---------------------------------------------------------------------------
__global__ __launch_bounds__(256) void k_scatter(const int* __restrict__ src,
                                                 const int* __restrict__ dst,
                                                 float* __restrict__ out) {
    int gid = blockIdx.x * 256 + threadIdx.x;
    int e = gid >> 4;
    if (e >= Ee) return;
    int t  = gid & 15;          // slice 0..15 (4 floats each)
    int hh = t >> 1;            // head of this slice
    int s = src[e];
    int d = dst[e];

    float4 w = *(const float4*)&g_Wh[(size_t)s * HO + t * 4];
    float attn = g_p[e * Hh + hh] / g_denom[d * Hh + hh];

    float4 v;
    v.x = w.x * attn; v.y = w.y * attn; v.z = w.z * attn; v.w = w.w * attn;

    float* addr = out + (size_t)d * HO + t * 4;   // 16B aligned
    asm volatile("red.global.add.v4.f32 [%0], {%1,%2,%3,%4};"
                 :: "l"(addr), "f"(v.x), "f"(v.y), "f"(v.z), "f"(v.w)
                 : "memory");
}

// ---------------------------------------------------------------------------
extern "C" void kernel_launch(void* const* d_in, const int* in_sizes, int n_in,
                              void* d_out, int out_size) {
    const float* h  = (const float*)d_in[0];
    const float* W  = (const float*)d_in[1];
    const float* a1 = (const float*)d_in[2];
    const float* a2 = (const float*)d_in[3];
    const int*  src = (const int*)d_in[4];
    const int*  dst = (const int*)d_in[5];
    float* out = (float*)d_out;

    cudaMemsetAsync(out, 0, (size_t)Nn * HO * sizeof(float));
    k_zero_denom<<<(Nn * Hh + 255) / 256, 256>>>();
    k_proj<<<Nn / 16, 256>>>(h, W, a1, a2);
    k_edge<<<(Ee * Hh) / 256, 256>>>(src, dst);
    k_scatter<<<(Ee * 16) / 256, 256>>>(src, dst, out);
}

// round 2
// speedup vs baseline: 1.1790x; 1.1790x over previous
#include <cuda_runtime.h>
#include <cuda_bf16.h>

// Problem shape (fixed for GAT_40870908789103)
#define Nn   50000
#define Ee   800000
#define Fin  128
#define Hh   8
#define Oo   8
#define HO   64          // H*O
#define NEG_SLOPE 0.2f

// Scratch (no allocation allowed -> __device__ globals)
__device__ float g_Wh[(size_t)Nn * HO];     // projected features [N][64]
__device__ float g_ssrc[(size_t)Nn * Hh];   // a1 . Wh[n,h,:]
__device__ float g_sdst[(size_t)Nn * Hh];   // a2 . Wh[n,h,:]
__device__ float g_denom[(size_t)Nn * Hh];  // softmax denominators

// ---------------------------------------------------------------------------
// K1: Wh = h @ W (per head), plus per-node half-scores s_src, s_dst.
// 256 threads, 16 rows/block. Thread = (row r, head, half): computes 4
// consecutive outputs -> 1 scalar LDS + 1 LDS.128 per 4 FMAs.
// Also zeroes g_denom for this row (runs before the scatter kernel).
// 50000 % 16 == 0, so no row guards needed.
// ---------------------------------------------------------------------------
__global__ __launch_bounds__(256) void k_proj(const float* __restrict__ h,
                                              const float* __restrict__ W,
                                              const float* __restrict__ a1,
                                              const float* __restrict__ a2) {
    __shared__ float Wt[Fin * HO];     // W transposed to [f][64], 32KB
    __shared__ float hs[16 * Fin];     // 16 input rows, 8KB
    __shared__ float a1s[HO], a2s[HO];

    const int tid = threadIdx.x;

    // Load + transpose W: W[h][f][o] -> Wt[f*64 + h*8 + o]
    for (int i = tid; i < Fin * HO; i += 256) {
        int hidx = i >> 10;        // / (Fin*Oo)
        int rem  = i & 1023;
        int f    = rem >> 3;
        int o    = rem & 7;
        Wt[f * 64 + hidx * 8 + o] = W[i];
    }
    if (tid < HO) { a1s[tid] = a1[tid]; a2s[tid] = a2[tid]; }

    const int row0 = blockIdx.x * 16;
    for (int i = tid; i < 16 * Fin; i += 256) {
        hs[i] = h[(size_t)(row0 + (i >> 7)) * Fin + (i & 127)];
    }
    __syncthreads();

    const int r    = tid >> 4;         // 0..15 row within chunk
    const int head = (tid >> 1) & 7;   // 0..7
    const int half = tid & 1;          // 0..1
    const int col  = head * 8 + half * 4;

    float4 acc = make_float4(0.f, 0.f, 0.f, 0.f);
    const float* hrow = &hs[r * Fin];
    #pragma unroll 16
    for (int f = 0; f < Fin; f++) {
        float  hv = hrow[f];
        float4 w  = *(const float4*)&Wt[f * 64 + col];
        acc.x += hv * w.x; acc.y += hv * w.y;
        acc.z += hv * w.z; acc.w += hv * w.w;
    }

    const int row = row0 + r;
    *(float4*)&g_Wh[(size_t)row * HO + col] = acc;

    float s1 = acc.x * a1s[col] + acc.y * a1s[col + 1] +
               acc.z * a1s[col + 2] + acc.w * a1s[col + 3];
    float s2 = acc.x * a2s[col] + acc.y * a2s[col + 1] +
               acc.z * a2s[col + 2] + acc.w * a2s[col + 3];
    s1 += __shfl_xor_sync(0xffffffffu, s1, 1);
    s2 += __shfl_xor_sync(0xffffffffu, s2, 1);
    if (half == 0) {
        g_ssrc[row * Hh + head]  = s1;
        g_sdst[row * Hh + head]  = s2;
        g_denom[row * Hh + head] = 0.0f;   // zero denominators for scatter
    }
}

// ---------------------------------------------------------------------------
// K2: fused edge pass. 16 threads/edge (slice t = 0..15, head = t>>1).
// Recomputes p = exp(leaky_relu(s_src[src] + s_dst[dst])) from the tiny
// L2-resident s tables; accumulates BOTH the softmax denominator and the
// UNNORMALIZED message sum (division deferred to k_norm). Max-subtraction
// skipped: |logit| <~ 30, exp stays far below fp32 overflow, and the
// normalized result is analytically identical.
// ---------------------------------------------------------------------------
__global__ __launch_bounds__(256) void k_scatter(const int* __restrict__ src,
                                                 const int* __restrict__ dst,
                                                 float* __restrict__ out) {
    int gid = blockIdx.x * 256 + threadIdx.x;
    int e = gid >> 4;
    if (e >= Ee) return;
    int t  = gid & 15;          // slice 0..15 (4 floats each)
    int hh = t >> 1;            // head of this slice
    int s = __ldg(&src[e]);
    int d = __ldg(&dst[e]);

    float ev = g_ssrc[s * Hh + hh] + g_sdst[d * Hh + hh];
    ev = ev > 0.0f ? ev : NEG_SLOPE * ev;
    float pv = __expf(ev);

    float4 w = *(const float4*)&g_Wh[(size_t)s * HO + t * 4];

    // one lane per (edge, head) accumulates the denominator
    if ((t & 1) == 0) {
        asm volatile("red.global.add.f32 [%0], %1;"
                     :: "l"(&g_denom[d * Hh + hh]), "f"(pv) : "memory");
    }

    float4 v;
    v.x = w.x * pv; v.y = w.y * pv; v.z = w.z * pv; v.w = w.w * pv;

    float* addr = out + (size_t)d * HO + t * 4;   // 16B aligned
    asm volatile("red.global.add.v4.f32 [%0], {%1,%2,%3,%4};"
                 :: "l"(addr), "f"(v.x), "f"(v.y), "f"(v.z), "f"(v.w)
                 : "memory");
}

// ---------------------------------------------------------------------------
// K3: deferred softmax normalization: out[n,h,:] /= max(denom[n,h], 1e-16).
// One float4 per thread; 12.8MB rw, stream-bound (~4us).
// ---------------------------------------------------------------------------
__global__ __launch_bounds__(256) void k_norm(float* __restrict__ out) {
    int i = blockIdx.x * 256 + threadIdx.x;     // over N*16 float4 slices
    if (i >= Nn * 16) return;
    int n  = i >> 4;
    int t  = i & 15;
    int hh = t >> 1;
    float dnm = g_denom[n * Hh + hh];
    float inv = 1.0f / fmaxf(dnm, 1e-16f);
    float4* p = (float4*)(out + (size_t)n * HO + t * 4);
    float4 v = *p;
    v.x *= inv; v.y *= inv; v.z *= inv; v.w *= inv;
    *p = v;
}

// ---------------------------------------------------------------------------
extern "C" void kernel_launch(void* const* d_in, const int* in_sizes, int n_in,
                              void* d_out, int out_size) {
    const float* h  = (const float*)d_in[0];
    const float* W  = (const float*)d_in[1];
    const float* a1 = (const float*)d_in[2];
    const float* a2 = (const float*)d_in[3];
    const int*  src = (const int*)d_in[4];
    const int*  dst = (const int*)d_in[5];
    float* out = (float*)d_out;

    cudaMemsetAsync(out, 0, (size_t)Nn * HO * sizeof(float));
    k_proj<<<Nn / 16, 256>>>(h, W, a1, a2);
    k_scatter<<<(Ee * 16) / 256, 256>>>(src, dst, out);
    k_norm<<<(Nn * 16 + 255) / 256, 256>>>(out);
}

// round 3
// speedup vs baseline: 1.7327x; 1.4696x over previous
#include <cuda_runtime.h>
#include <cuda_bf16.h>

// Problem shape (fixed for GAT_40870908789103)
#define Nn   50000
#define Ee   800000
#define Fin  128
#define Hh   8
#define Oo   8
#define HO   64          // H*O
#define NEG_SLOPE 0.2f

// Scratch (no allocation allowed -> __device__ globals)
__device__ float g_Wh[(size_t)Nn * HO];     // projected features [N][64]
__device__ float g_ssrc[(size_t)Nn * Hh];   // a1 . Wh[n,h,:]
__device__ float g_sdst[(size_t)Nn * Hh];   // a2 . Wh[n,h,:]
__device__ float g_denom[(size_t)Nn * Hh];  // softmax denominators

// ---------------------------------------------------------------------------
// K1: Wh = h @ W, register-blocked 8x8 per thread.
// Block = 128 threads, tile = 128 rows x 64 cols. Thread (rg,cg) computes
// rows rg*8..rg*8+7 for cols cg*8..cg*8+7 (cols of one head = cg).
// Per f-step: 2 LDS.128 (W, 32B) + 8 scalar LDS (h, conflict-free via
// stride-33 padding) feed 64 FMAs -> ~1B/FMA crossbar traffic.
// F processed in 4 chunks of 32 to keep smem at ~25KB (static limit 48KB).
// Also emits s_src, s_dst (in-register dot with a1/a2) and zeroes g_denom.
// ---------------------------------------------------------------------------
#define FCH 32                      // f-chunk
#define HS_STRIDE 33                // 32 + 1 pad: bank = (row+f) % 32

__global__ __launch_bounds__(128) void k_proj(const float* __restrict__ h,
                                              const float* __restrict__ W,
                                              const float* __restrict__ a1,
                                              const float* __restrict__ a2) {
    __shared__ float Wt[FCH * HO];          // [f_local][64], 8KB
    __shared__ float hs[128 * HS_STRIDE];   // [row][f_local] padded, 16.9KB

    const int tid = threadIdx.x;
    const int rg  = tid >> 3;               // 0..15 (8 rows each)
    const int cg  = tid & 7;                // 0..7  (head index, 8 cols)
    const int row0 = blockIdx.x * 128;

    float4 acc0[8], acc1[8];
    #pragma unroll
    for (int j = 0; j < 8; j++) {
        acc0[j] = make_float4(0.f, 0.f, 0.f, 0.f);
        acc1[j] = make_float4(0.f, 0.f, 0.f, 0.f);
    }

    for (int fc = 0; fc < Fin; fc += FCH) {
        // Load + transpose W chunk: W[h][fc+fl][o] -> Wt[fl*64 + h*8 + o]
        for (int i = tid; i < FCH * HO; i += 128) {
            int fl  = i >> 6;
            int col = i & 63;
            int hh  = col >> 3;
            int o   = col & 7;
            Wt[i] = W[(size_t)hh * (Fin * Oo) + (fc + fl) * Oo + o];
        }
        // Load h chunk: 128 rows x 32 f as float4 (coalesced), store padded.
        // STS banks: (row + 4*f4 + j) mod 32 -> conflict-free across warp.
        for (int i = tid; i < 128 * (FCH / 4); i += 128) {
            int row  = i >> 3;
            int f4   = i & 7;
            int grow = row0 + row;
            if (grow >= Nn) grow = Nn - 1;          // clamp (harmless dup)
            float4 v = *(const float4*)&h[(size_t)grow * Fin + fc + f4 * 4];
            float* dstp = &hs[row * HS_STRIDE + f4 * 4];
            dstp[0] = v.x; dstp[1] = v.y; dstp[2] = v.z; dstp[3] = v.w;
        }
        __syncthreads();

        #pragma unroll 4
        for (int f = 0; f < FCH; f++) {
            float4 w0 = *(const float4*)&Wt[f * 64 + cg * 8];
            float4 w1 = *(const float4*)&Wt[f * 64 + cg * 8 + 4];
            #pragma unroll
            for (int j = 0; j < 8; j++) {
                float hv = hs[(rg * 8 + j) * HS_STRIDE + f];
                acc0[j].x += hv * w0.x; acc0[j].y += hv * w0.y;
                acc0[j].z += hv * w0.z; acc0[j].w += hv * w0.w;
                acc1[j].x += hv * w1.x; acc1[j].y += hv * w1.y;
                acc1[j].z += hv * w1.z; acc1[j].w += hv * w1.w;
            }
        }
        __syncthreads();
    }

    // Epilogue: store Wh + per-head half-scores (thread owns full head cg).
    float4 a1lo = *(const float4*)&a1[cg * 8];
    float4 a1hi = *(const float4*)&a1[cg * 8 + 4];
    float4 a2lo = *(const float4*)&a2[cg * 8];
    float4 a2hi = *(const float4*)&a2[cg * 8 + 4];

    #pragma unroll
    for (int j = 0; j < 8; j++) {
        int row = row0 + rg * 8 + j;
        if (row < Nn) {
            *(float4*)&g_Wh[(size_t)row * HO + cg * 8]     = acc0[j];
            *(float4*)&g_Wh[(size_t)row * HO + cg * 8 + 4] = acc1[j];
            float s1 = acc0[j].x * a1lo.x + acc0[j].y * a1lo.y +
                       acc0[j].z * a1lo.z + acc0[j].w * a1lo.w +
                       acc1[j].x * a1hi.x + acc1[j].y * a1hi.y +
                       acc1[j].z * a1hi.z + acc1[j].w * a1hi.w;
            float s2 = acc0[j].x * a2lo.x + acc0[j].y * a2lo.y +
                       acc0[j].z * a2lo.z + acc0[j].w * a2lo.w +
                       acc1[j].x * a2hi.x + acc1[j].y * a2hi.y +
                       acc1[j].z * a2hi.z + acc1[j].w * a2hi.w;
            g_ssrc[row * Hh + cg]  = s1;
            g_sdst[row * Hh + cg]  = s2;
            g_denom[row * Hh + cg] = 0.0f;
        }
    }
}

// ---------------------------------------------------------------------------
// K2: fused edge pass. 16 threads/edge (slice t = 0..15, head = t>>1).
// Recomputes p = exp(leaky_relu(s_src[src] + s_dst[dst])) from the tiny
// L2-resident s tables; accumulates BOTH the softmax denominator and the
// UNNORMALIZED message sum (division deferred to k_norm). Max-subtraction
// skipped: |logit| <~ 30, exp stays far below fp32 overflow, and the
// normalized result is analytically identical.
// ---------------------------------------------------------------------------
__global__ __launch_bounds__(256) void k_scatter(const int* __restrict__ src,
                                                 const int* __restrict__ dst,
                                                 float* __restrict__ out) {
    int gid = blockIdx.x * 256 + threadIdx.x;
    int e = gid >> 4;
    if (e >= Ee) return;
    int t  = gid & 15;          // slice 0..15 (4 floats each)
    int hh = t >> 1;            // head of this slice
    int s = __ldg(&src[e]);
    int d = __ldg(&dst[e]);

    float ev = g_ssrc[s * Hh + hh] + g_sdst[d * Hh + hh];
    ev = ev > 0.0f ? ev : NEG_SLOPE * ev;
    float pv = __expf(ev);

    float4 w = *(const float4*)&g_Wh[(size_t)s * HO + t * 4];

    // one lane per (edge, head) accumulates the denominator
    if ((t & 1) == 0) {
        asm volatile("red.global.add.f32 [%0], %1;"
                     :: "l"(&g_denom[d * Hh + hh]), "f"(pv) : "memory");
    }

    float4 v;
    v.x = w.x * pv; v.y = w.y * pv; v.z = w.z * pv; v.w = w.w * pv;

    float* addr = out + (size_t)d * HO + t * 4;   // 16B aligned
    asm volatile("red.global.add.v4.f32 [%0], {%1,%2,%3,%4};"
                 :: "l"(addr), "f"(v.x), "f"(v.y), "f"(v.z), "f"(v.w)
                 : "memory");
}

// ---------------------------------------------------------------------------
// K3: deferred softmax normalization: out[n,h,:] /= max(denom[n,h], 1e-16).
// ---------------------------------------------------------------------------
__global__ __launch_bounds__(256) void k_norm(float* __restrict__ out) {
    int i = blockIdx.x * 256 + threadIdx.x;     // over N*16 float4 slices
    if (i >= Nn * 16) return;
    int n  = i >> 4;
    int t  = i & 15;
    int hh = t >> 1;
    float dnm = g_denom[n * Hh + hh];
    float inv = 1.0f / fmaxf(dnm, 1e-16f);
    float4* p = (float4*)(out + (size_t)n * HO + t * 4);
    float4 v = *p;
    v.x *= inv; v.y *= inv; v.z *= inv; v.w *= inv;
    *p = v;
}

// ---------------------------------------------------------------------------
extern "C" void kernel_launch(void* const* d_in, const int* in_sizes, int n_in,
                              void* d_out, int out_size) {
    const float* h  = (const float*)d_in[0];
    const float* W  = (const float*)d_in[1];
    const float* a1 = (const float*)d_in[2];
    const float* a2 = (const float*)d_in[3];
    const int*  src = (const int*)d_in[4];
    const int*  dst = (const int*)d_in[5];
    float* out = (float*)d_out;

    cudaMemsetAsync(out, 0, (size_t)Nn * HO * sizeof(float));
    k_proj<<<(Nn + 127) / 128, 128>>>(h, W, a1, a2);
    k_scatter<<<(Ee * 16) / 256, 256>>>(src, dst, out);
    k_norm<<<(Nn * 16 + 255) / 256, 256>>>(out);
}